// round 16
// baseline (speedup 1.0000x reference)
#include <cuda_runtime.h>
#include <cuda_fp16.h>
#include <stdint.h>
#include <math.h>

#define BB 32
#define SS 2048
#define DD 128
#define BQ 128
#define BK 64
#define NITER (SS / BK)
#define NTH 512

// ===========================================================================
// threefry (partitionable, key (0,42)) — verified bit-exact R2/R8/R9/R10
// ===========================================================================
__device__ __forceinline__ uint32_t rotl32(uint32_t x, int r) {
    return __funnelshift_l(x, x, r);
}
#define TF_ROUND(r) do { x0 += x1; x1 = rotl32(x1, (r)); x1 ^= x0; } while (0)
__device__ __forceinline__ uint32_t threefry_fold_0_42(uint32_t c1) {
    const uint32_t ks1 = 42u, ks2 = 42u ^ 0x1BD11BDAu;
    uint32_t x0 = 0u, x1 = c1 + ks1;
    TF_ROUND(13); TF_ROUND(15); TF_ROUND(26); TF_ROUND(6);
    x0 += ks1; x1 += ks2 + 1u;
    TF_ROUND(17); TF_ROUND(29); TF_ROUND(16); TF_ROUND(24);
    x0 += ks2; x1 += 0u + 2u;
    TF_ROUND(13); TF_ROUND(15); TF_ROUND(26); TF_ROUND(6);
    x0 += 0u; x1 += ks1 + 3u;
    TF_ROUND(17); TF_ROUND(29); TF_ROUND(16); TF_ROUND(24);
    x0 += ks1; x1 += ks2 + 4u;
    TF_ROUND(13); TF_ROUND(15); TF_ROUND(26); TF_ROUND(6);
    x0 += ks2; x1 += 0u + 5u;
    return x0 ^ x1;
}
__device__ __forceinline__ uint32_t hash8_scatter(uint32_t cb) {
    const uint32_t TH = 3006477312u;    // 5872026 << 9
    uint32_t acc = 0u;
#pragma unroll
    for (int nt = 0; nt < 4; nt++) {
#pragma unroll
        for (int e = 0; e < 2; e++) {
            uint32_t bits = threefry_fold_0_42(cb + (uint32_t)(nt * 8 + e));
            acc |= (bits < TH) ? (1u << (nt * 2 + e)) : 0u;
        }
    }
    return acc;
}

// ===========================================================================
// fp16 mma + pack helpers
// ===========================================================================
__device__ __forceinline__ void mma_f16(float* c, const uint32_t* a,
                                        uint32_t b0, uint32_t b1) {
    asm volatile(
        "mma.sync.aligned.m16n8k16.row.col.f32.f16.f16.f32 "
        "{%0,%1,%2,%3}, {%4,%5,%6,%7}, {%8,%9}, {%0,%1,%2,%3};"
        : "+f"(c[0]), "+f"(c[1]), "+f"(c[2]), "+f"(c[3])
        : "r"(a[0]), "r"(a[1]), "r"(a[2]), "r"(a[3]), "r"(b0), "r"(b1));
}
__device__ __forceinline__ uint32_t packh2(float lo, float hi) {
    uint32_t d;
    asm("cvt.rn.f16x2.f32 %0, %1, %2;" : "=r"(d) : "f"(hi), "f"(lo));
    return d;
}
__device__ __forceinline__ float2 h2f2(uint32_t h) {
    __half2 v = *reinterpret_cast<__half2*>(&h);
    return __half22float2(v);
}
__device__ __forceinline__ void split2(float x, float y, uint32_t& hw, uint32_t& lw) {
    hw = packh2(x, y);
    float2 f = h2f2(hw);
    lw = packh2(x - f.x, y - f.y);
}
__device__ __forceinline__ uint32_t smem_u32(const void* p) {
    uint32_t a;
    asm("{ .reg .u64 t; cvta.to.shared.u64 t, %1; cvt.u32.u64 %0, t; }"
        : "=r"(a) : "l"(p));
    return a;
}
__device__ __forceinline__ void cp16(uint32_t saddr, const void* g) {
    asm volatile("cp.async.cg.shared.global [%0], [%1], 16;"
                 :: "r"(saddr), "l"(g) : "memory");
}
#define CP_COMMIT() asm volatile("cp.async.commit_group;" ::: "memory")
#define CP_WAIT(n)  asm volatile("cp.async.wait_group %0;" :: "n"(n) : "memory")

// ---- smem layout (word strides) ----
#define QPSTR 68
#define KPSTR 68
#define KRSTR 132
#define VRSTR 132
#define VPSTR 136
#define PPSTR 36

#define OFF_QH 0
#define OFF_QL (OFF_QH + 128 * QPSTR * 4)    // 34816
#define OFF_KRAW (OFF_QL + 128 * QPSTR * 4)  // 69632
#define OFF_KH (OFF_KRAW + 64 * KRSTR * 4)   // 103424
#define OFF_KL (OFF_KH + 64 * KPSTR * 4)     // 120832
#define OFF_VRAW (OFF_KL + 64 * KPSTR * 4)   // 138240
#define OFF_VP (OFF_VRAW + 64 * VRSTR * 4)   // 172032
#define OFF_PP (OFF_VP + 32 * VPSTR * 4)     // 189440
#define OFF_MX (OFF_PP + 128 * PPSTR * 4)    // 207872
#define OFF_SM (OFF_MX + 1024)               // 208896
#define SMEM_BYTES (OFF_SM + 1024)           // 209920

__global__ void __launch_bounds__(NTH) attn_mma(
    const float* __restrict__ q, const float* __restrict__ k,
    const float* __restrict__ v, const float* __restrict__ scale,
    float* __restrict__ out) {
    extern __shared__ char smem_raw[];
    uint32_t* QH = (uint32_t*)(smem_raw + OFF_QH);
    uint32_t* QL = (uint32_t*)(smem_raw + OFF_QL);
    float* KRAW = (float*)(smem_raw + OFF_KRAW);
    uint32_t* KH = (uint32_t*)(smem_raw + OFF_KH);
    uint32_t* KL = (uint32_t*)(smem_raw + OFF_KL);
    float* VRAW = (float*)(smem_raw + OFF_VRAW);
    uint32_t* VP = (uint32_t*)(smem_raw + OFF_VP);
    uint32_t* PP = (uint32_t*)(smem_raw + OFF_PP);
    float* PMX = (float*)(smem_raw + OFF_MX);
    float* PSM = (float*)(smem_raw + OFF_SM);
    const uint32_t sb = smem_u32(smem_raw);
    const uint32_t sbKR = sb + OFF_KRAW;
    const uint32_t sbVR = sb + OFF_VRAW;

    const int tid = threadIdx.x;
    const int lane = tid & 31;
    const int w = tid >> 5;
    const int rb = w >> 1;
    const int ch = w & 1;
    const int g = lane >> 2;
    const int tig = lane & 3;
    const int wrow = rb * 16;
    const int b = blockIdx.y;
    const int q0 = blockIdx.x * BQ;

    const float* kb = k + (size_t)b * SS * DD;
    const float* vb = v + (size_t)b * SS * DD;

    const int ldrow = tid >> 5;       // 0..15
    const int ldc = tid & 31;         // float4 chunk 0..31
    const int ldc4 = ldc * 4;
    // V ownership: keypair kp, 8-float column slice (loader map == pack map)
    const int vkp = tid >> 4;         // 0..31
    const int vd0 = (tid & 15) * 8;   // 0..120

    // ---- preload tile 0: {K0}, {V0} ----
#pragma unroll
    for (int i = 0; i < 4; i++) {
        int row = ldrow + i * 16;
        cp16(sbKR + (uint32_t)(row * KRSTR + ldc4) * 4u, kb + row * DD + ldc4);
    }
    CP_COMMIT();
#pragma unroll
    for (int r2 = 0; r2 < 2; r2++)
#pragma unroll
        for (int j = 0; j < 2; j++) {
            int row = 2 * vkp + r2, c = vd0 + j * 4;
            cp16(sbVR + (uint32_t)(row * VRSTR + c) * 4u, vb + row * DD + c);
        }
    CP_COMMIT();

    // ---- prologue: load Q, scale, split to packed fp16 hi/lo ----
    {
        const float sc = scale[b];
        const float* qb = q + ((size_t)b * SS + q0) * DD;
#pragma unroll
        for (int i = 0; i < 8; i++) {
            int f = tid + i * NTH;
            int row = f >> 5, cq = f & 31;
            float4 x = *(const float4*)(qb + row * DD + cq * 4);
            uint32_t h0, l0w, h1, l1w;
            split2(x.x * sc, x.y * sc, h0, l0w);
            split2(x.z * sc, x.w * sc, h1, l1w);
            *(uint2*)(QH + row * QPSTR + cq * 2) = make_uint2(h0, h1);
            *(uint2*)(QL + row * QPSTR + cq * 2) = make_uint2(l0w, l1w);
        }
    }

    const int r0 = wrow + g;
    const int r1 = wrow + g + 8;
    const int gi0 = q0 + r0;
    const int gi1 = q0 + r1;
    const uint32_t cbase0 = (((uint32_t)b << 11) + (uint32_t)gi0) * 2048u
                            + (uint32_t)ch * 32u + (uint32_t)tig * 2u;
    const uint32_t cbase1 = (((uint32_t)b << 11) + (uint32_t)gi1) * 2048u
                            + (uint32_t)ch * 32u + (uint32_t)tig * 2u;
    const float L2E = 1.4426950408889634f;
    const float DEAD = -17.3286795139986f;   // -25*ln2: below this, fp16(e)==0
    const uint32_t FM = 0xffffffffu;

    float m0 = -INFINITY, m1 = -INFINITY, l0 = 0.f, l1 = 0.f;
    float O[8][4];
#pragma unroll
    for (int nt = 0; nt < 8; nt++)
#pragma unroll
        for (int e = 0; e < 4; e++) O[nt][e] = 0.f;

    for (int t = 0; t < NITER; t++) {
        CP_WAIT(1);   // K(t) landed (thread-owned slots)

        // ---- split K(t): thread-owned (same map as loader) ----
#pragma unroll
        for (int i = 0; i < 4; i++) {
            int row = ldrow + i * 16;
            float4 x = *(const float4*)(KRAW + row * KRSTR + ldc4);
            uint32_t h0, l0w, h1, l1w;
            split2(x.x, x.y, h0, l0w);
            split2(x.z, x.w, h1, l1w);
            *(uint2*)(KH + row * KPSTR + ldc * 2) = make_uint2(h0, h1);
            *(uint2*)(KL + row * KPSTR + ldc * 2) = make_uint2(l0w, l1w);
        }
        // ---- prefetch raw K(t+1) into same thread-owned slots ----
        if (t + 1 < NITER) {
            const float* kt = kb + (size_t)(t + 1) * BK * DD;
#pragma unroll
            for (int i = 0; i < 4; i++) {
                int row = ldrow + i * 16;
                cp16(sbKR + (uint32_t)(row * KRSTR + ldc4) * 4u, kt + row * DD + ldc4);
            }
        }
        CP_COMMIT();       // pending {V(t), K(t+1)}
        __syncthreads();   // B: KH/KL visible block-wide

        // ---- gemm1: 3-pass split-fp16 k16 ----
        float S[4][4];
#pragma unroll
        for (int nt = 0; nt < 4; nt++)
#pragma unroll
            for (int e = 0; e < 4; e++) S[nt][e] = 0.f;

#pragma unroll 1
        for (int ks = 0; ks < 8; ks++) {
            const int wq = ks * 8 + tig;
            uint32_t ah[4], al[4];
            ah[0] = QH[r0 * QPSTR + wq];     al[0] = QL[r0 * QPSTR + wq];
            ah[1] = QH[r1 * QPSTR + wq];     al[1] = QL[r1 * QPSTR + wq];
            ah[2] = QH[r0 * QPSTR + wq + 4]; al[2] = QL[r0 * QPSTR + wq + 4];
            ah[3] = QH[r1 * QPSTR + wq + 4]; al[3] = QL[r1 * QPSTR + wq + 4];
#pragma unroll
            for (int nt = 0; nt < 4; nt++) {
                const int j = (ch * 32 + nt * 8 + g) * KPSTR;
                uint32_t bh0 = KH[j + wq], bh1 = KH[j + wq + 4];
                uint32_t bl0 = KL[j + wq], bl1 = KL[j + wq + 4];
                mma_f16(S[nt], ah, bh0, bh1);
                mma_f16(S[nt], ah, bl0, bl1);
                mma_f16(S[nt], al, bh0, bh1);
            }
        }

        // ---- partial row max ----
        float rmax0 = -INFINITY, rmax1 = -INFINITY;
#pragma unroll
        for (int nt = 0; nt < 4; nt++) {
            rmax0 = fmaxf(rmax0, fmaxf(S[nt][0], S[nt][1]));
            rmax1 = fmaxf(rmax1, fmaxf(S[nt][2], S[nt][3]));
        }
        rmax0 = fmaxf(rmax0, __shfl_xor_sync(FM, rmax0, 1));
        rmax0 = fmaxf(rmax0, __shfl_xor_sync(FM, rmax0, 2));
        rmax1 = fmaxf(rmax1, __shfl_xor_sync(FM, rmax1, 1));
        rmax1 = fmaxf(rmax1, __shfl_xor_sync(FM, rmax1, 2));
        PMX[ch * 128 + r0] = rmax0;
        PMX[ch * 128 + r1] = rmax1;
        __syncthreads();   // C: pmax visible

        const float rfull0 = fmaxf(PMX[r0], PMX[128 + r0]);
        const float rfull1 = fmaxf(PMX[r1], PMX[128 + r1]);
        const float mn0 = fmaxf(m0, rfull0);
        const float mn1 = fmaxf(m1, rfull1);
        const float fr0 = exp2f((m0 - mn0) * L2E);
        const float fr1 = exp2f((m1 - mn1) * L2E);
        const bool live0 = (rmax0 - mn0) > DEAD;
        const bool live1 = (rmax1 - mn1) > DEAD;
        const bool livef0 = (rfull0 - mn0) > DEAD;
        const bool livef1 = (rfull1 - mn1) > DEAD;

        // ---- V(t): wait, pack (thread-owned), prefetch V(t+1) ----
        CP_WAIT(1);        // V(t) landed (pending {K(t+1)})
        {
#pragma unroll
            for (int j = 0; j < 2; j++) {
                const int c = vd0 + j * 4;
                float4 a = *(const float4*)(VRAW + (2 * vkp) * VRSTR + c);
                float4 c2 = *(const float4*)(VRAW + (2 * vkp + 1) * VRSTR + c);
                uint4 o;
                o.x = packh2(a.x, c2.x);
                o.y = packh2(a.y, c2.y);
                o.z = packh2(a.z, c2.z);
                o.w = packh2(a.w, c2.w);
                *(uint4*)(VP + vkp * VPSTR + c) = o;
            }
        }
        if (t + 1 < NITER) {
            const float* vt = vb + (size_t)(t + 1) * BK * DD;
#pragma unroll
            for (int r2 = 0; r2 < 2; r2++)
#pragma unroll
                for (int j = 0; j < 2; j++) {
                    int row = 2 * vkp + r2, c = vd0 + j * 4;
                    cp16(sbVR + (uint32_t)(row * VRSTR + c) * 4u, vt + row * DD + c);
                }
        }
        CP_COMMIT();       // pending {K(t+1), V(t+1)}

        // ---- dropout hash + exp + masked P store ----
        float rs0 = 0.f, rs1 = 0.f;
        if (live0) {
            const uint32_t mk = hash8_scatter(cbase0 + (uint32_t)t * 64u);
#pragma unroll
            for (int nt = 0; nt < 4; nt++) {
                float e00 = exp2f((S[nt][0] - mn0) * L2E);
                float e01 = exp2f((S[nt][1] - mn0) * L2E);
                rs0 += e00 + e01;
                float d00 = ((mk >> (nt * 2)) & 1u) ? e00 : 0.f;
                float d01 = ((mk >> (nt * 2 + 1)) & 1u) ? e01 : 0.f;
                PP[r0 * PPSTR + ch * 16 + nt * 4 + tig] = packh2(d00, d01);
            }
        } else {
#pragma unroll
            for (int nt = 0; nt < 4; nt++)
                PP[r0 * PPSTR + ch * 16 + nt * 4 + tig] = 0u;
        }
        if (live1) {
            const uint32_t mk = hash8_scatter(cbase1 + (uint32_t)t * 64u);
#pragma unroll
            for (int nt = 0; nt < 4; nt++) {
                float e10 = exp2f((S[nt][2] - mn1) * L2E);
                float e11 = exp2f((S[nt][3] - mn1) * L2E);
                rs1 += e10 + e11;
                float d10 = ((mk >> (nt * 2)) & 1u) ? e10 : 0.f;
                float d11 = ((mk >> (nt * 2 + 1)) & 1u) ? e11 : 0.f;
                PP[r1 * PPSTR + ch * 16 + nt * 4 + tig] = packh2(d10, d11);
            }
        } else {
#pragma unroll
            for (int nt = 0; nt < 4; nt++)
                PP[r1 * PPSTR + ch * 16 + nt * 4 + tig] = 0u;
        }
        rs0 += __shfl_xor_sync(FM, rs0, 1);
        rs0 += __shfl_xor_sync(FM, rs0, 2);
        rs1 += __shfl_xor_sync(FM, rs1, 1);
        rs1 += __shfl_xor_sync(FM, rs1, 2);
        PSM[ch * 128 + r0] = rs0;
        PSM[ch * 128 + r1] = rs1;

        const bool skip2 = __all_sync(FM, !(livef0 || livef1));
        __syncthreads();   // D: PP + PSM + VP visible

        l0 = l0 * fr0 + PSM[r0] + PSM[128 + r0];
        l1 = l1 * fr1 + PSM[r1] + PSM[128 + r1];
        m0 = mn0; m1 = mn1;

        if (!skip2) {
#pragma unroll
            for (int nt = 0; nt < 8; nt++) {
                O[nt][0] *= fr0; O[nt][1] *= fr0;
                O[nt][2] *= fr1; O[nt][3] *= fr1;
            }
#pragma unroll 1
            for (int ks = 0; ks < 4; ks++) {
                const int wp = ks * 8 + tig;
                uint32_t pa[4];
                pa[0] = PP[r0 * PPSTR + wp];
                pa[1] = PP[r1 * PPSTR + wp];
                pa[2] = PP[r0 * PPSTR + wp + 4];
                pa[3] = PP[r1 * PPSTR + wp + 4];
#pragma unroll
                for (int nt = 0; nt < 8; nt++) {
                    const int col = ch * 64 + nt * 8 + g;
                    uint32_t vb0 = VP[wp * VPSTR + col];
                    uint32_t vb1 = VP[(wp + 4) * VPSTR + col];
                    mma_f16(O[nt], pa, vb0, vb1);
                }
            }
        }
    }

    // ---- epilogue ----
    const float inv0 = 1.f / (l0 * 0.7f);
    const float inv1 = 1.f / (l1 * 0.7f);
    float* o0 = out + ((size_t)b * SS + gi0) * DD + ch * 64;
    float* o1 = out + ((size_t)b * SS + gi1) * DD + ch * 64;
#pragma unroll
    for (int nt = 0; nt < 8; nt++) {
        const int c = nt * 8 + 2 * tig;
        *(float2*)(o0 + c) = make_float2(O[nt][0] * inv0, O[nt][1] * inv0);
        *(float2*)(o1 + c) = make_float2(O[nt][2] * inv1, O[nt][3] * inv1);
    }
}

// ---------------------------------------------------------------------------
extern "C" void kernel_launch(void* const* d_in, const int* in_sizes, int n_in,
                              void* d_out, int out_size) {
    (void)in_sizes; (void)n_in; (void)out_size;
    const float* q = (const float*)d_in[0];
    const float* k = (const float*)d_in[1];
    const float* v = (const float*)d_in[2];
    const float* scale = (const float*)d_in[3];
    float* out = (float*)d_out;

    static const bool _init = []() {
        cudaFuncSetAttribute(attn_mma,
                             cudaFuncAttributeMaxDynamicSharedMemorySize,
                             SMEM_BYTES);
        return true;
    }();
    (void)_init;

    dim3 grid(SS / BQ, BB);
    attn_mma<<<grid, NTH, SMEM_BYTES>>>(q, k, v, scale, out);
}

// round 17
// speedup vs baseline: 1.0859x; 1.0859x over previous
#include <cuda_runtime.h>
#include <cuda_fp16.h>
#include <stdint.h>
#include <math.h>

#define BB 32
#define SS 2048
#define DD 128
#define BQ 128
#define BK 64
#define NITER (SS / BK)
#define NTH 512

// ===========================================================================
// threefry (partitionable, key (0,42)) — verified bit-exact R2/R8/R9/R10
// ===========================================================================
__device__ __forceinline__ uint32_t rotl32(uint32_t x, int r) {
    return __funnelshift_l(x, x, r);
}
#define TF_ROUND(r) do { x0 += x1; x1 = rotl32(x1, (r)); x1 ^= x0; } while (0)
__device__ __forceinline__ uint32_t threefry_fold_0_42(uint32_t c1) {
    const uint32_t ks1 = 42u, ks2 = 42u ^ 0x1BD11BDAu;
    uint32_t x0 = 0u, x1 = c1 + ks1;
    TF_ROUND(13); TF_ROUND(15); TF_ROUND(26); TF_ROUND(6);
    x0 += ks1; x1 += ks2 + 1u;
    TF_ROUND(17); TF_ROUND(29); TF_ROUND(16); TF_ROUND(24);
    x0 += ks2; x1 += 0u + 2u;
    TF_ROUND(13); TF_ROUND(15); TF_ROUND(26); TF_ROUND(6);
    x0 += 0u; x1 += ks1 + 3u;
    TF_ROUND(17); TF_ROUND(29); TF_ROUND(16); TF_ROUND(24);
    x0 += ks1; x1 += ks2 + 4u;
    TF_ROUND(13); TF_ROUND(15); TF_ROUND(26); TF_ROUND(6);
    x0 += ks2; x1 += 0u + 5u;
    return x0 ^ x1;
}
__device__ __forceinline__ uint32_t hash8_scatter(uint32_t cb) {
    const uint32_t TH = 3006477312u;    // 5872026 << 9
    uint32_t acc = 0u;
#pragma unroll
    for (int nt = 0; nt < 4; nt++) {
#pragma unroll
        for (int e = 0; e < 2; e++) {
            uint32_t bits = threefry_fold_0_42(cb + (uint32_t)(nt * 8 + e));
            acc |= (bits < TH) ? (1u << (nt * 2 + e)) : 0u;
        }
    }
    return acc;
}

// ===========================================================================
// fp16 mma + pack helpers
// ===========================================================================
__device__ __forceinline__ void mma_f16(float* c, const uint32_t* a,
                                        uint32_t b0, uint32_t b1) {
    asm volatile(
        "mma.sync.aligned.m16n8k16.row.col.f32.f16.f16.f32 "
        "{%0,%1,%2,%3}, {%4,%5,%6,%7}, {%8,%9}, {%0,%1,%2,%3};"
        : "+f"(c[0]), "+f"(c[1]), "+f"(c[2]), "+f"(c[3])
        : "r"(a[0]), "r"(a[1]), "r"(a[2]), "r"(a[3]), "r"(b0), "r"(b1));
}
__device__ __forceinline__ uint32_t packh2(float lo, float hi) {
    uint32_t d;
    asm("cvt.rn.f16x2.f32 %0, %1, %2;" : "=r"(d) : "f"(hi), "f"(lo));
    return d;
}
__device__ __forceinline__ float2 h2f2(uint32_t h) {
    __half2 v = *reinterpret_cast<__half2*>(&h);
    return __half22float2(v);
}
__device__ __forceinline__ void split2(float x, float y, uint32_t& hw, uint32_t& lw) {
    hw = packh2(x, y);
    float2 f = h2f2(hw);
    lw = packh2(x - f.x, y - f.y);
}
__device__ __forceinline__ uint32_t smem_u32(const void* p) {
    uint32_t a;
    asm("{ .reg .u64 t; cvta.to.shared.u64 t, %1; cvt.u32.u64 %0, t; }"
        : "=r"(a) : "l"(p));
    return a;
}
__device__ __forceinline__ void cp16(uint32_t saddr, const void* g) {
    asm volatile("cp.async.cg.shared.global [%0], [%1], 16;"
                 :: "r"(saddr), "l"(g) : "memory");
}
#define CP_COMMIT() asm volatile("cp.async.commit_group;" ::: "memory")
#define CP_WAIT(n)  asm volatile("cp.async.wait_group %0;" :: "n"(n) : "memory")

// ---- smem layout (word strides) ----
#define QPSTR 68
#define KPSTR 68
#define KRSTR 132
#define VRSTR 132
#define VPSTR 136
#define PPSTR 36

#define OFF_QH 0
#define OFF_QL (OFF_QH + 128 * QPSTR * 4)    // 34816
#define OFF_KRAW (OFF_QL + 128 * QPSTR * 4)  // 69632
#define OFF_KH (OFF_KRAW + 64 * KRSTR * 4)   // 103424
#define OFF_KL (OFF_KH + 64 * KPSTR * 4)     // 120832
#define OFF_VRAW (OFF_KL + 64 * KPSTR * 4)   // 138240
#define OFF_VP (OFF_VRAW + 64 * VRSTR * 4)   // 172032
#define OFF_PP (OFF_VP + 32 * VPSTR * 4)     // 189440
#define OFF_MX (OFF_PP + 128 * PPSTR * 4)    // 207872
#define OFF_SM (OFF_MX + 1024)               // 208896
#define SMEM_BYTES (OFF_SM + 1024)           // 209920

__global__ void __launch_bounds__(NTH) attn_mma(
    const float* __restrict__ q, const float* __restrict__ k,
    const float* __restrict__ v, const float* __restrict__ scale,
    float* __restrict__ out) {
    extern __shared__ char smem_raw[];
    uint32_t* QH = (uint32_t*)(smem_raw + OFF_QH);
    uint32_t* QL = (uint32_t*)(smem_raw + OFF_QL);
    float* KRAW = (float*)(smem_raw + OFF_KRAW);
    uint32_t* KH = (uint32_t*)(smem_raw + OFF_KH);
    uint32_t* KL = (uint32_t*)(smem_raw + OFF_KL);
    float* VRAW = (float*)(smem_raw + OFF_VRAW);
    uint32_t* VP = (uint32_t*)(smem_raw + OFF_VP);
    uint32_t* PP = (uint32_t*)(smem_raw + OFF_PP);
    float* PMX = (float*)(smem_raw + OFF_MX);
    float* PSM = (float*)(smem_raw + OFF_SM);
    const uint32_t sb = smem_u32(smem_raw);
    const uint32_t sbKR = sb + OFF_KRAW;
    const uint32_t sbVR = sb + OFF_VRAW;

    const int tid = threadIdx.x;
    const int lane = tid & 31;
    const int w = tid >> 5;
    const int rb = w >> 1;
    const int ch = w & 1;
    const int g = lane >> 2;
    const int tig = lane & 3;
    const int wrow = rb * 16;
    const int b = blockIdx.y;
    const int q0 = blockIdx.x * BQ;

    const float* kb = k + (size_t)b * SS * DD;
    const float* vb = v + (size_t)b * SS * DD;

    const int ldrow = tid >> 5;       // 0..15
    const int ldc = tid & 31;         // float4 chunk 0..31
    const int ldc4 = ldc * 4;
    // V ownership: keypair kp, 8-float column slice (loader map == pack map)
    const int vkp = tid >> 4;         // 0..31
    const int vd0 = (tid & 15) * 8;   // 0..120

    // ---- preload tile 0: {K0}, {V0} ----
#pragma unroll
    for (int i = 0; i < 4; i++) {
        int row = ldrow + i * 16;
        cp16(sbKR + (uint32_t)(row * KRSTR + ldc4) * 4u, kb + row * DD + ldc4);
    }
    CP_COMMIT();
#pragma unroll
    for (int r2 = 0; r2 < 2; r2++)
#pragma unroll
        for (int j = 0; j < 2; j++) {
            int row = 2 * vkp + r2, c = vd0 + j * 4;
            cp16(sbVR + (uint32_t)(row * VRSTR + c) * 4u, vb + row * DD + c);
        }
    CP_COMMIT();

    // ---- prologue: load Q, scale, split to packed fp16 hi/lo ----
    {
        const float sc = scale[b];
        const float* qb = q + ((size_t)b * SS + q0) * DD;
#pragma unroll
        for (int i = 0; i < 8; i++) {
            int f = tid + i * NTH;
            int row = f >> 5, cq = f & 31;
            float4 x = *(const float4*)(qb + row * DD + cq * 4);
            uint32_t h0, l0w, h1, l1w;
            split2(x.x * sc, x.y * sc, h0, l0w);
            split2(x.z * sc, x.w * sc, h1, l1w);
            *(uint2*)(QH + row * QPSTR + cq * 2) = make_uint2(h0, h1);
            *(uint2*)(QL + row * QPSTR + cq * 2) = make_uint2(l0w, l1w);
        }
    }

    const int r0 = wrow + g;
    const int r1 = wrow + g + 8;
    const int gi0 = q0 + r0;
    const int gi1 = q0 + r1;
    const uint32_t cbase0 = (((uint32_t)b << 11) + (uint32_t)gi0) * 2048u
                            + (uint32_t)ch * 32u + (uint32_t)tig * 2u;
    const uint32_t cbase1 = (((uint32_t)b << 11) + (uint32_t)gi1) * 2048u
                            + (uint32_t)ch * 32u + (uint32_t)tig * 2u;
    const float L2E = 1.4426950408889634f;
    const float DEAD = -17.3286795139986f;   // -25*ln2: below this, fp16(e)==0
    const uint32_t FM = 0xffffffffu;

    float m0 = -INFINITY, m1 = -INFINITY, l0 = 0.f, l1 = 0.f;
    float O[8][4];
#pragma unroll
    for (int nt = 0; nt < 8; nt++)
#pragma unroll
        for (int e = 0; e < 4; e++) O[nt][e] = 0.f;

    for (int t = 0; t < NITER; t++) {
        CP_WAIT(1);   // K(t) landed (thread-owned slots)

        // ---- split K(t): thread-owned (same map as loader) ----
#pragma unroll
        for (int i = 0; i < 4; i++) {
            int row = ldrow + i * 16;
            float4 x = *(const float4*)(KRAW + row * KRSTR + ldc4);
            uint32_t h0, l0w, h1, l1w;
            split2(x.x, x.y, h0, l0w);
            split2(x.z, x.w, h1, l1w);
            *(uint2*)(KH + row * KPSTR + ldc * 2) = make_uint2(h0, h1);
            *(uint2*)(KL + row * KPSTR + ldc * 2) = make_uint2(l0w, l1w);
        }
        // ---- prefetch raw K(t+1) into same thread-owned slots ----
        if (t + 1 < NITER) {
            const float* kt = kb + (size_t)(t + 1) * BK * DD;
#pragma unroll
            for (int i = 0; i < 4; i++) {
                int row = ldrow + i * 16;
                cp16(sbKR + (uint32_t)(row * KRSTR + ldc4) * 4u, kt + row * DD + ldc4);
            }
        }
        CP_COMMIT();       // pending {V(t), K(t+1)}
        __syncthreads();   // B: KH/KL visible block-wide

        // ---- gemm1: 3-pass split-fp16 k16 ----
        float S[4][4];
#pragma unroll
        for (int nt = 0; nt < 4; nt++)
#pragma unroll
            for (int e = 0; e < 4; e++) S[nt][e] = 0.f;

#pragma unroll 1
        for (int ks = 0; ks < 8; ks++) {
            const int wq = ks * 8 + tig;
            uint32_t ah[4], al[4];
            ah[0] = QH[r0 * QPSTR + wq];     al[0] = QL[r0 * QPSTR + wq];
            ah[1] = QH[r1 * QPSTR + wq];     al[1] = QL[r1 * QPSTR + wq];
            ah[2] = QH[r0 * QPSTR + wq + 4]; al[2] = QL[r0 * QPSTR + wq + 4];
            ah[3] = QH[r1 * QPSTR + wq + 4]; al[3] = QL[r1 * QPSTR + wq + 4];
#pragma unroll
            for (int nt = 0; nt < 4; nt++) {
                const int j = (ch * 32 + nt * 8 + g) * KPSTR;
                uint32_t bh0 = KH[j + wq], bh1 = KH[j + wq + 4];
                uint32_t bl0 = KL[j + wq], bl1 = KL[j + wq + 4];
                mma_f16(S[nt], ah, bh0, bh1);
                mma_f16(S[nt], ah, bl0, bl1);
                mma_f16(S[nt], al, bh0, bh1);
            }
        }

        // ---- partial row max ----
        float rmax0 = -INFINITY, rmax1 = -INFINITY;
#pragma unroll
        for (int nt = 0; nt < 4; nt++) {
            rmax0 = fmaxf(rmax0, fmaxf(S[nt][0], S[nt][1]));
            rmax1 = fmaxf(rmax1, fmaxf(S[nt][2], S[nt][3]));
        }
        rmax0 = fmaxf(rmax0, __shfl_xor_sync(FM, rmax0, 1));
        rmax0 = fmaxf(rmax0, __shfl_xor_sync(FM, rmax0, 2));
        rmax1 = fmaxf(rmax1, __shfl_xor_sync(FM, rmax1, 1));
        rmax1 = fmaxf(rmax1, __shfl_xor_sync(FM, rmax1, 2));
        PMX[ch * 128 + r0] = rmax0;
        PMX[ch * 128 + r1] = rmax1;
        __syncthreads();   // C: pmax visible

        const float rfull0 = fmaxf(PMX[r0], PMX[128 + r0]);
        const float rfull1 = fmaxf(PMX[r1], PMX[128 + r1]);
        const float mn0 = fmaxf(m0, rfull0);
        const float mn1 = fmaxf(m1, rfull1);
        const float fr0 = exp2f((m0 - mn0) * L2E);
        const float fr1 = exp2f((m1 - mn1) * L2E);
        const bool live0 = (rmax0 - mn0) > DEAD;
        const bool live1 = (rmax1 - mn1) > DEAD;
        const bool livef0 = (rfull0 - mn0) > DEAD;
        const bool livef1 = (rfull1 - mn1) > DEAD;

        // ---- dropout hash + exp + masked P store ----
        float rs0 = 0.f, rs1 = 0.f;
        if (live0) {
            const uint32_t mk = hash8_scatter(cbase0 + (uint32_t)t * 64u);
#pragma unroll
            for (int nt = 0; nt < 4; nt++) {
                float e00 = exp2f((S[nt][0] - mn0) * L2E);
                float e01 = exp2f((S[nt][1] - mn0) * L2E);
                rs0 += e00 + e01;
                float d00 = ((mk >> (nt * 2)) & 1u) ? e00 : 0.f;
                float d01 = ((mk >> (nt * 2 + 1)) & 1u) ? e01 : 0.f;
                PP[r0 * PPSTR + ch * 16 + nt * 4 + tig] = packh2(d00, d01);
            }
        } else {
#pragma unroll
            for (int nt = 0; nt < 4; nt++)
                PP[r0 * PPSTR + ch * 16 + nt * 4 + tig] = 0u;
        }
        if (live1) {
            const uint32_t mk = hash8_scatter(cbase1 + (uint32_t)t * 64u);
#pragma unroll
            for (int nt = 0; nt < 4; nt++) {
                float e10 = exp2f((S[nt][2] - mn1) * L2E);
                float e11 = exp2f((S[nt][3] - mn1) * L2E);
                rs1 += e10 + e11;
                float d10 = ((mk >> (nt * 2)) & 1u) ? e10 : 0.f;
                float d11 = ((mk >> (nt * 2 + 1)) & 1u) ? e11 : 0.f;
                PP[r1 * PPSTR + ch * 16 + nt * 4 + tig] = packh2(d10, d11);
            }
        } else {
#pragma unroll
            for (int nt = 0; nt < 4; nt++)
                PP[r1 * PPSTR + ch * 16 + nt * 4 + tig] = 0u;
        }
        rs0 += __shfl_xor_sync(FM, rs0, 1);
        rs0 += __shfl_xor_sync(FM, rs0, 2);
        rs1 += __shfl_xor_sync(FM, rs1, 1);
        rs1 += __shfl_xor_sync(FM, rs1, 2);
        PSM[ch * 128 + r0] = rs0;
        PSM[ch * 128 + r1] = rs1;

        const bool skip2 = __all_sync(FM, !(livef0 || livef1));

        // ---- V(t): wait (late, full prefetch cover), pack, prefetch V(t+1) ----
        CP_WAIT(1);        // V(t) landed (pending {K(t+1)})
#pragma unroll
        for (int j = 0; j < 2; j++) {
            const int c = vd0 + j * 4;
            float4 a = *(const float4*)(VRAW + (2 * vkp) * VRSTR + c);
            float4 c2 = *(const float4*)(VRAW + (2 * vkp + 1) * VRSTR + c);
            uint4 o;
            o.x = packh2(a.x, c2.x);
            o.y = packh2(a.y, c2.y);
            o.z = packh2(a.z, c2.z);
            o.w = packh2(a.w, c2.w);
            *(uint4*)(VP + vkp * VPSTR + c) = o;
        }
        if (t + 1 < NITER) {
            const float* vt = vb + (size_t)(t + 1) * BK * DD;
#pragma unroll
            for (int r2 = 0; r2 < 2; r2++)
#pragma unroll
                for (int j = 0; j < 2; j++) {
                    int row = 2 * vkp + r2, c = vd0 + j * 4;
                    cp16(sbVR + (uint32_t)(row * VRSTR + c) * 4u, vt + row * DD + c);
                }
        }
        CP_COMMIT();       // pending {K(t+1), V(t+1)}

        __syncthreads();   // D: PP + PSM + VP visible

        l0 = l0 * fr0 + PSM[r0] + PSM[128 + r0];
        l1 = l1 * fr1 + PSM[r1] + PSM[128 + r1];
        m0 = mn0; m1 = mn1;

        if (!skip2) {
#pragma unroll
            for (int nt = 0; nt < 8; nt++) {
                O[nt][0] *= fr0; O[nt][1] *= fr0;
                O[nt][2] *= fr1; O[nt][3] *= fr1;
            }
#pragma unroll 1
            for (int ks = 0; ks < 4; ks++) {
                const int wp = ks * 8 + tig;
                uint32_t pa[4];
                pa[0] = PP[r0 * PPSTR + wp];
                pa[1] = PP[r1 * PPSTR + wp];
                pa[2] = PP[r0 * PPSTR + wp + 4];
                pa[3] = PP[r1 * PPSTR + wp + 4];
#pragma unroll
                for (int nt = 0; nt < 8; nt++) {
                    const int col = ch * 64 + nt * 8 + g;
                    uint32_t vb0 = VP[wp * VPSTR + col];
                    uint32_t vb1 = VP[(wp + 4) * VPSTR + col];
                    mma_f16(O[nt], pa, vb0, vb1);
                }
            }
        }
    }

    // ---- epilogue ----
    const float inv0 = 1.f / (l0 * 0.7f);
    const float inv1 = 1.f / (l1 * 0.7f);
    float* o0 = out + ((size_t)b * SS + gi0) * DD + ch * 64;
    float* o1 = out + ((size_t)b * SS + gi1) * DD + ch * 64;
#pragma unroll
    for (int nt = 0; nt < 8; nt++) {
        const int c = nt * 8 + 2 * tig;
        *(float2*)(o0 + c) = make_float2(O[nt][0] * inv0, O[nt][1] * inv0);
        *(float2*)(o1 + c) = make_float2(O[nt][2] * inv1, O[nt][3] * inv1);
    }
}

// ---------------------------------------------------------------------------
extern "C" void kernel_launch(void* const* d_in, const int* in_sizes, int n_in,
                              void* d_out, int out_size) {
    (void)in_sizes; (void)n_in; (void)out_size;
    const float* q = (const float*)d_in[0];
    const float* k = (const float*)d_in[1];
    const float* v = (const float*)d_in[2];
    const float* scale = (const float*)d_in[3];
    float* out = (float*)d_out;

    static const bool _init = []() {
        cudaFuncSetAttribute(attn_mma,
                             cudaFuncAttributeMaxDynamicSharedMemorySize,
                             SMEM_BYTES);
        return true;
    }();
    (void)_init;

    dim3 grid(SS / BQ, BB);
    attn_mma<<<grid, NTH, SMEM_BYTES>>>(q, k, v, scale, out);
}